// round 4
// baseline (speedup 1.0000x reference)
#include <cuda_runtime.h>
#include <math.h>

#define MAXN 102400
#define MAXE 1605632
#define NBMAX 64

// ---------------- device scratch (zero-initialized at module load) -----------
__device__ int    g_cnt[MAXN];           // per-row counts (re-zeroed by scatter)
__device__ int    g_rank[MAXE];          // within-row rank of each edge
__device__ int    g_rowptr[MAXN + 1];    // block-local exclusive starts
__device__ int    g_bsums[NBMAX];
__device__ int    g_boffs[NBMAX];        // block offsets (add to rowptr)
__device__ int    g_done;                // decoupled-scan counter (self-reset)
__device__ int2   g_csr[MAXE];           // (col, ew bits)
__device__ float4 g_A4[MAXN * 4];        // xp0 - xp1
__device__ float4 g_B4[MAXN * 4];        // dinv * xp1 (layer-1 gather target)
__device__ float4 g_h4[MAXN * 4];        // h = relu(...)
__device__ float4 g_hs4[MAXN * 4];       // dinv * h   (layer-2 gather target)
__device__ float  g_dinv[MAXN];

// ---------------- per-block edge-index dtype detection -----------------------
// int64 nonneg < 2^31 -> every odd 32-bit word of the first 128 words is 0.
__device__ __forceinline__ int detect_is64(const int* w) {
    int bad = 0;
    #pragma unroll
    for (int j = 1; j < 128; j += 2) bad |= w[j];
    return bad == 0;
}

// ---------------- pass 1: counts + within-row rank (2 edges/thread) ----------
__global__ void k_cnt(const void* __restrict__ ei, int E) {
    __shared__ int s_is64;
    if (threadIdx.x == 0) s_is64 = detect_is64((const int*)ei);
    __syncthreads();
    int e = (blockIdx.x * blockDim.x + threadIdx.x) * 2;
    if (e >= E) return;
    int r0, r1 = -1;
    if (s_is64) {
        longlong2 v = *(const longlong2*)((const long long*)ei + e);
        r0 = (int)v.x;
        if (e + 1 < E) r1 = (int)v.y;
    } else {
        int2 v = *(const int2*)((const int*)ei + e);
        r0 = v.x;
        if (e + 1 < E) r1 = v.y;
    }
    g_rank[e] = atomicAdd(&g_cnt[r0], 1);
    if (r1 >= 0) g_rank[e + 1] = atomicAdd(&g_cnt[r1], 1);
}

// ---------------- scan: per-block local scan + decoupled block-offset scan ---
__global__ void k_scan_local(int N, int E, int NB) {
    __shared__ int warpSums[32];
    __shared__ int s_flag;
    __shared__ int s_boffs[NBMAX];
    int t = threadIdx.x;
    int base = blockIdx.x * 2048;
    int i0 = base + 2 * t, i1 = i0 + 1;
    int v0 = (i0 < N) ? g_cnt[i0] : 0;
    int v1 = (i1 < N) ? g_cnt[i1] : 0;
    int s = v0 + v1;
    int lane = t & 31, wid = t >> 5;
    int incl = s;
    #pragma unroll
    for (int d = 1; d < 32; d <<= 1) {
        int n = __shfl_up_sync(0xffffffffu, incl, d);
        if (lane >= d) incl += n;
    }
    if (lane == 31) warpSums[wid] = incl;
    __syncthreads();
    if (wid == 0) {
        int ws = warpSums[lane];
        int wi = ws;
        #pragma unroll
        for (int d = 1; d < 32; d <<= 1) {
            int n = __shfl_up_sync(0xffffffffu, wi, d);
            if (lane >= d) wi += n;
        }
        warpSums[lane] = wi - ws;
    }
    __syncthreads();
    int excl = warpSums[wid] + incl - s;
    if (i0 < N) g_rowptr[i0] = excl;
    if (i1 < N) g_rowptr[i1] = excl + v0;
    if (t == 1023) g_bsums[blockIdx.x] = warpSums[wid] + incl;

    // decoupled finish: last block to arrive scans the <=64 block sums
    __syncthreads();
    if (t == 0) {
        __threadfence();
        s_flag = (atomicAdd(&g_done, 1) == NB - 1);
    }
    __syncthreads();
    if (s_flag && t < 32) {
        __threadfence();
        int b0 = (lane < NB) ? g_bsums[lane] : 0;
        int b1 = (lane + 32 < NB) ? g_bsums[lane + 32] : 0;
        int i0s = b0;
        #pragma unroll
        for (int d = 1; d < 32; d <<= 1) {
            int n = __shfl_up_sync(0xffffffffu, i0s, d);
            if (lane >= d) i0s += n;
        }
        int tot0 = __shfl_sync(0xffffffffu, i0s, 31);
        int i1s = b1;
        #pragma unroll
        for (int d = 1; d < 32; d <<= 1) {
            int n = __shfl_up_sync(0xffffffffu, i1s, d);
            if (lane >= d) i1s += n;
        }
        i1s += tot0;
        int e0 = i0s - b0, e1 = i1s - b1;
        g_boffs[lane] = e0;
        g_boffs[lane + 32] = e1;
        s_boffs[lane] = e0;
        s_boffs[lane + 32] = e1;
        __syncwarp();
        if (lane == 0) {
            g_rowptr[N] = E - s_boffs[N >> 11];   // sentinel (local coords)
            g_done = 0;                            // reset for next replay
        }
    }
}

// ---------------- pass 2: scatter into CSR (1 random load + 1 random store) --
__global__ void k_scatter(const void* __restrict__ ei, const float* __restrict__ ew, int E) {
    __shared__ int s_is64;
    __shared__ int s_boffs[NBMAX];
    if (threadIdx.x == 0) s_is64 = detect_is64((const int*)ei);
    if (threadIdx.x < NBMAX) s_boffs[threadIdx.x] = g_boffs[threadIdx.x];
    __syncthreads();
    int e = blockIdx.x * blockDim.x + threadIdx.x;
    if (e < E) {
        int r, c;
        if (s_is64) {
            r = (int)((const long long*)ei)[e];
            c = (int)((const long long*)ei)[(long)E + e];
        } else {
            r = ((const int*)ei)[e];
            c = ((const int*)ei)[E + e];
        }
        float w = ew[e];
        int p = g_rowptr[r] + s_boffs[r >> 11] + g_rank[e];
        g_csr[p] = make_int2(c, __float_as_int(w));
    }
    if (e < MAXN) g_cnt[e] = 0;   // reset counts for next graph replay
}

// ---------------- GEMM1: A = x@W0 - x@W1, B = dinv*(x@W1) --------------------
// 8 warps x 4 nodes per block; weighted degree via coalesced CSR sweep.
__global__ void k_gemm1(const float* __restrict__ x,
                        const float* __restrict__ W0,
                        const float* __restrict__ W1, int N) {
    __shared__ float  Wsh[128 * 32];
    __shared__ float4 xs[8][4][32];
    __shared__ float  dvs[8][4];
    __shared__ int    s_boffs[NBMAX];
    int t = threadIdx.x;
    if (t < NBMAX) s_boffs[t] = g_boffs[t];
    for (int i = t; i < 128 * 16; i += 256) {
        int k = i >> 4, j = i & 15;
        Wsh[k * 32 + j]      = W0[i];
        Wsh[k * 32 + 16 + j] = W1[i];
    }
    __syncthreads();   // boffs + Wsh ready

    int warp = t >> 5, lane = t & 31;
    int base = (blockIdx.x * 8 + warp) * 4;

    // weighted degree: 8 lanes per node, coalesced CSR reads
    {
        int g = lane >> 3, l8 = lane & 7;
        int node = base + g;
        float dsum = 0.f;
        if (node < N) {
            int s = g_rowptr[node] + s_boffs[node >> 11];
            int e = g_rowptr[node + 1] + s_boffs[(node + 1) >> 11];
            for (int p = s + l8; p < e; p += 8)
                dsum += __int_as_float(g_csr[p].y);
        }
        dsum += __shfl_xor_sync(0xffffffffu, dsum, 1);
        dsum += __shfl_xor_sync(0xffffffffu, dsum, 2);
        dsum += __shfl_xor_sync(0xffffffffu, dsum, 4);
        float dv = (dsum > 0.f) ? rsqrtf(dsum) : 0.f;
        if (l8 == 0 && node < N) { g_dinv[node] = dv; dvs[warp][g] = dv; }
    }

    #pragma unroll
    for (int n = 0; n < 4; n++) {
        int nd = base + n;
        float4 v = make_float4(0.f, 0.f, 0.f, 0.f);
        if (nd < N) v = ((const float4*)(x + (size_t)nd * 128))[lane];
        xs[warp][n][lane] = v;
    }
    __syncthreads();

    float a0 = 0.f, a1 = 0.f, a2 = 0.f, a3 = 0.f;
    #pragma unroll
    for (int k4 = 0; k4 < 32; k4++) {
        float w0 = Wsh[(k4 * 4 + 0) * 32 + lane];
        float w1 = Wsh[(k4 * 4 + 1) * 32 + lane];
        float w2 = Wsh[(k4 * 4 + 2) * 32 + lane];
        float w3 = Wsh[(k4 * 4 + 3) * 32 + lane];
        float4 b0 = xs[warp][0][k4];
        float4 b1 = xs[warp][1][k4];
        float4 b2 = xs[warp][2][k4];
        float4 b3 = xs[warp][3][k4];
        a0 = fmaf(b0.x, w0, fmaf(b0.y, w1, fmaf(b0.z, w2, fmaf(b0.w, w3, a0))));
        a1 = fmaf(b1.x, w0, fmaf(b1.y, w1, fmaf(b1.z, w2, fmaf(b1.w, w3, a1))));
        a2 = fmaf(b2.x, w0, fmaf(b2.y, w1, fmaf(b2.z, w2, fmaf(b2.w, w3, a2))));
        a3 = fmaf(b3.x, w0, fmaf(b3.y, w1, fmaf(b3.z, w2, fmaf(b3.w, w3, a3))));
    }

    float* A = (float*)g_A4;
    float* B = (float*)g_B4;
    float acc[4] = {a0, a1, a2, a3};
    #pragma unroll
    for (int n = 0; n < 4; n++) {
        int nd = base + n;
        float a = acc[n];
        float o = __shfl_xor_sync(0xffffffffu, a, 16);
        if (nd < N) {
            float dv = dvs[warp][n];
            if (lane < 16) A[(size_t)nd * 16 + lane] = a - o;          // xp0 - xp1
            else           B[(size_t)nd * 16 + (lane - 16)] = dv * a;  // dinv*xp1
        }
    }
}

// ---------------- layer1: h = relu(A + dinv*agg(B) + b1) ---------------------
__global__ void k_layer1(const float* __restrict__ b1, int N) {
    __shared__ int s_boffs[NBMAX];
    if (threadIdx.x < NBMAX) s_boffs[threadIdx.x] = g_boffs[threadIdx.x];
    __syncthreads();
    int t = blockIdx.x * blockDim.x + threadIdx.x;
    int row = t >> 5;
    if (row >= N) return;
    int lane = t & 31, q = lane & 3, slot = lane >> 2;
    int s = g_rowptr[row] + s_boffs[row >> 11];
    int e = g_rowptr[row + 1] + s_boffs[(row + 1) >> 11];
    float4 acc = make_float4(0.f, 0.f, 0.f, 0.f);
    for (int p = s + slot; p < e; p += 8) {
        int2 ce = g_csr[p];
        float nv = __int_as_float(ce.y);
        float4 v = g_B4[(size_t)ce.x * 4 + q];
        acc.x = fmaf(nv, v.x, acc.x);
        acc.y = fmaf(nv, v.y, acc.y);
        acc.z = fmaf(nv, v.z, acc.z);
        acc.w = fmaf(nv, v.w, acc.w);
    }
    #pragma unroll
    for (int d = 4; d < 32; d <<= 1) {
        acc.x += __shfl_xor_sync(0xffffffffu, acc.x, d);
        acc.y += __shfl_xor_sync(0xffffffffu, acc.y, d);
        acc.z += __shfl_xor_sync(0xffffffffu, acc.z, d);
        acc.w += __shfl_xor_sync(0xffffffffu, acc.w, d);
    }
    if (lane < 4) {
        float dv = g_dinv[row];
        float4 A  = g_A4[(size_t)row * 4 + lane];
        float4 bb = ((const float4*)b1)[lane];
        float4 h;
        h.x = fmaxf(A.x + dv * acc.x + bb.x, 0.f);
        h.y = fmaxf(A.y + dv * acc.y + bb.y, 0.f);
        h.z = fmaxf(A.z + dv * acc.z + bb.z, 0.f);
        h.w = fmaxf(A.w + dv * acc.w + bb.w, 0.f);
        g_h4[(size_t)row * 4 + lane]  = h;
        g_hs4[(size_t)row * 4 + lane] = make_float4(dv * h.x, dv * h.y, dv * h.z, dv * h.w);
    }
}

// ---------------- layer2: agg(hs) + dual GEMV + log_softmax ------------------
__global__ void k_layer2(const float* __restrict__ W20,
                         const float* __restrict__ W21,
                         const float* __restrict__ b2,
                         float* __restrict__ out, int N) {
    __shared__ float Wd[16 * 32];   // W20 - W21
    __shared__ float Wb[16 * 32];   // W21
    __shared__ int   s_boffs[NBMAX];
    int t = threadIdx.x;
    if (t < NBMAX) s_boffs[t] = g_boffs[t];
    for (int i = t; i < 512; i += blockDim.x) {
        float w1v = W21[i];
        Wd[i] = W20[i] - w1v;
        Wb[i] = w1v;
    }
    __syncthreads();
    int gt = blockIdx.x * blockDim.x + t;
    int row = gt >> 5;
    if (row >= N) return;
    int lane = t & 31, q = lane & 3, slot = lane >> 2;
    int s = g_rowptr[row] + s_boffs[row >> 11];
    int e = g_rowptr[row + 1] + s_boffs[(row + 1) >> 11];
    float4 acc = make_float4(0.f, 0.f, 0.f, 0.f);
    for (int p = s + slot; p < e; p += 8) {
        int2 ce = g_csr[p];
        float nv = __int_as_float(ce.y);
        float4 v = g_hs4[(size_t)ce.x * 4 + q];
        acc.x = fmaf(nv, v.x, acc.x);
        acc.y = fmaf(nv, v.y, acc.y);
        acc.z = fmaf(nv, v.z, acc.z);
        acc.w = fmaf(nv, v.w, acc.w);
    }
    #pragma unroll
    for (int d = 4; d < 32; d <<= 1) {
        acc.x += __shfl_xor_sync(0xffffffffu, acc.x, d);
        acc.y += __shfl_xor_sync(0xffffffffu, acc.y, d);
        acc.z += __shfl_xor_sync(0xffffffffu, acc.z, d);
        acc.w += __shfl_xor_sync(0xffffffffu, acc.w, d);
    }
    float4 hv = make_float4(0.f, 0.f, 0.f, 0.f);
    if (lane < 4) hv = g_h4[(size_t)row * 4 + lane];
    float dv = g_dinv[row];

    float sh = 0.f, sa = 0.f;
    #pragma unroll
    for (int f = 0; f < 16; f++) {
        int src = f >> 2;
        float ch, ca;
        if ((f & 3) == 0)      { ch = hv.x; ca = acc.x; }
        else if ((f & 3) == 1) { ch = hv.y; ca = acc.y; }
        else if ((f & 3) == 2) { ch = hv.z; ca = acc.z; }
        else                   { ch = hv.w; ca = acc.w; }
        float hf = __shfl_sync(0xffffffffu, ch, src);
        float af = __shfl_sync(0xffffffffu, ca, src);
        sh = fmaf(hf, Wd[f * 32 + lane], sh);
        sa = fmaf(af, Wb[f * 32 + lane], sa);
    }
    float val = sh + dv * sa + __ldg(&b2[lane]);

    float m = val;
    #pragma unroll
    for (int d = 16; d; d >>= 1) m = fmaxf(m, __shfl_xor_sync(0xffffffffu, m, d));
    float ex = __expf(val - m);
    float sum = ex;
    #pragma unroll
    for (int d = 16; d; d >>= 1) sum += __shfl_xor_sync(0xffffffffu, sum, d);
    out[(size_t)row * 32 + lane] = val - m - __logf(sum);
}

// ---------------- launcher ----------------------------------------------------
extern "C" void kernel_launch(void* const* d_in, const int* in_sizes, int n_in,
                              void* d_out, int out_size) {
    const float* x   = (const float*)d_in[0];
    const void*  ei  = d_in[1];
    const float* ew  = (const float*)d_in[2];
    const float* W10 = (const float*)d_in[3];
    const float* W11 = (const float*)d_in[4];
    const float* b1  = (const float*)d_in[5];
    const float* W20 = (const float*)d_in[6];
    const float* W21 = (const float*)d_in[7];
    const float* b2  = (const float*)d_in[8];
    float* out = (float*)d_out;

    int N = in_sizes[0] / 128;
    int E = in_sizes[2];
    int NB = (N + 2047) / 2048;

    k_cnt<<<(E / 2 + 255) / 256, 256>>>(ei, E);
    k_scan_local<<<NB, 1024>>>(N, E, NB);
    k_scatter<<<(E + 255) / 256, 256>>>(ei, ew, E);
    k_gemm1<<<(N + 31) / 32, 256>>>(x, W10, W11, N);
    k_layer1<<<(N * 32 + 255) / 256, 256>>>(b1, N);
    k_layer2<<<(N * 32 + 255) / 256, 256>>>(W20, W21, b2, out, N);
}

// round 5
// speedup vs baseline: 1.4128x; 1.4128x over previous
#include <cuda_runtime.h>
#include <math.h>

#define MAXN 102400
#define MAXE 1605632
#define NBMAX 64

// ---------------- device scratch (zero-initialized at module load) -----------
__device__ int    g_cnt[MAXN];           // per-row counts (re-zeroed by scatter)
__device__ int    g_rank[MAXE];          // within-row rank of each edge
__device__ int    g_rowptr[MAXN + 1];    // block-local exclusive starts
__device__ int    g_bsums[NBMAX];
__device__ int    g_boffs[NBMAX];        // block offsets (add to rowptr)
__device__ int    g_done;                // decoupled-scan counter (self-reset)
__device__ int    g_rps[MAXN + 1];       // GLOBAL row starts (written by k_dinv)
__device__ int2   g_csr[MAXE];           // (col, ew bits)
__device__ float4 g_A4[MAXN * 4];        // xp0 - xp1
__device__ float4 g_B4[MAXN * 4];        // dinv * xp1 (layer-1 gather target)
__device__ float4 g_h4[MAXN * 4];        // h = relu(...)
__device__ float4 g_hs4[MAXN * 4];       // dinv * h   (layer-2 gather target)
__device__ float  g_dinv[MAXN];

// ---------------- per-block edge-index dtype detection -----------------------
__device__ __forceinline__ int detect_is64(const int* w) {
    int bad = 0;
    #pragma unroll
    for (int j = 1; j < 128; j += 2) bad |= w[j];
    return bad == 0;
}

// ---------------- pass 1: counts + within-row rank (2 edges/thread) ----------
__global__ void k_cnt(const void* __restrict__ ei, int E) {
    __shared__ int s_is64;
    if (threadIdx.x == 0) s_is64 = detect_is64((const int*)ei);
    __syncthreads();
    int e = (blockIdx.x * blockDim.x + threadIdx.x) * 2;
    if (e >= E) return;
    int r0, r1 = -1;
    if (s_is64) {
        longlong2 v = *(const longlong2*)((const long long*)ei + e);
        r0 = (int)v.x;
        if (e + 1 < E) r1 = (int)v.y;
    } else {
        int2 v = *(const int2*)((const int*)ei + e);
        r0 = v.x;
        if (e + 1 < E) r1 = v.y;
    }
    g_rank[e] = atomicAdd(&g_cnt[r0], 1);
    if (r1 >= 0) g_rank[e + 1] = atomicAdd(&g_cnt[r1], 1);
}

// ---------------- scan: per-block local scan + decoupled block-offset scan ---
__global__ void k_scan_local(int N, int E, int NB) {
    __shared__ int warpSums[32];
    __shared__ int s_flag;
    int t = threadIdx.x;
    int base = blockIdx.x * 2048;
    int i0 = base + 2 * t, i1 = i0 + 1;
    int v0 = (i0 < N) ? g_cnt[i0] : 0;
    int v1 = (i1 < N) ? g_cnt[i1] : 0;
    int s = v0 + v1;
    int lane = t & 31, wid = t >> 5;
    int incl = s;
    #pragma unroll
    for (int d = 1; d < 32; d <<= 1) {
        int n = __shfl_up_sync(0xffffffffu, incl, d);
        if (lane >= d) incl += n;
    }
    if (lane == 31) warpSums[wid] = incl;
    __syncthreads();
    if (wid == 0) {
        int ws = warpSums[lane];
        int wi = ws;
        #pragma unroll
        for (int d = 1; d < 32; d <<= 1) {
            int n = __shfl_up_sync(0xffffffffu, wi, d);
            if (lane >= d) wi += n;
        }
        warpSums[lane] = wi - ws;
    }
    __syncthreads();
    int excl = warpSums[wid] + incl - s;
    if (i0 < N) g_rowptr[i0] = excl;
    if (i1 < N) g_rowptr[i1] = excl + v0;
    if (t == 1023) g_bsums[blockIdx.x] = warpSums[wid] + incl;

    __syncthreads();
    if (t == 0) {
        __threadfence();
        s_flag = (atomicAdd(&g_done, 1) == NB - 1);
    }
    __syncthreads();
    if (s_flag && t < 32) {
        __threadfence();
        int b0 = (lane < NB) ? g_bsums[lane] : 0;
        int b1 = (lane + 32 < NB) ? g_bsums[lane + 32] : 0;
        int i0s = b0;
        #pragma unroll
        for (int d = 1; d < 32; d <<= 1) {
            int n = __shfl_up_sync(0xffffffffu, i0s, d);
            if (lane >= d) i0s += n;
        }
        int tot0 = __shfl_sync(0xffffffffu, i0s, 31);
        int i1s = b1;
        #pragma unroll
        for (int d = 1; d < 32; d <<= 1) {
            int n = __shfl_up_sync(0xffffffffu, i1s, d);
            if (lane >= d) i1s += n;
        }
        i1s += tot0;
        g_boffs[lane]      = i0s - b0;
        g_boffs[lane + 32] = i1s - b1;
        __syncwarp();
        if (lane == 0) {
            g_rowptr[N] = E - g_boffs[N >> 11];   // sentinel (local coords)
            g_done = 0;                            // reset for next replay
        }
    }
}

// ---------------- pass 2: scatter into CSR (1 random load + 1 random store) --
__global__ void k_scatter(const void* __restrict__ ei, const float* __restrict__ ew, int E) {
    __shared__ int s_is64;
    __shared__ int s_boffs[NBMAX];
    if (threadIdx.x == 0) s_is64 = detect_is64((const int*)ei);
    if (threadIdx.x < NBMAX) s_boffs[threadIdx.x] = g_boffs[threadIdx.x];
    __syncthreads();
    int e = blockIdx.x * blockDim.x + threadIdx.x;
    if (e < E) {
        int r, c;
        if (s_is64) {
            r = (int)((const long long*)ei)[e];
            c = (int)((const long long*)ei)[(long)E + e];
        } else {
            r = ((const int*)ei)[e];
            c = ((const int*)ei)[E + e];
        }
        float w = ew[e];
        int p = g_rowptr[r] + s_boffs[r >> 11] + g_rank[e];
        g_csr[p] = make_int2(c, __float_as_int(w));
    }
    if (e < MAXN) g_cnt[e] = 0;   // reset counts for next graph replay
}

// ---------------- dinv + global row starts (one warp per row) ----------------
__global__ void k_dinv(int N, int E) {
    __shared__ int s_boffs[NBMAX];
    if (threadIdx.x < NBMAX) s_boffs[threadIdx.x] = g_boffs[threadIdx.x];
    __syncthreads();
    int gt = blockIdx.x * blockDim.x + threadIdx.x;
    int row = gt >> 5, lane = gt & 31;
    if (row >= N) return;
    int s = g_rowptr[row] + s_boffs[row >> 11];
    int e = g_rowptr[row + 1] + s_boffs[(row + 1) >> 11];
    float dsum = 0.f;
    for (int p = s + lane; p < e; p += 32)
        dsum += __int_as_float(g_csr[p].y);
    #pragma unroll
    for (int d = 16; d; d >>= 1) dsum += __shfl_xor_sync(0xffffffffu, dsum, d);
    if (lane == 0) {
        g_dinv[row] = (dsum > 0.f) ? rsqrtf(dsum) : 0.f;
        g_rps[row] = s;
    }
    if (gt == 0) g_rps[N] = E;
}

// ---------------- GEMM1: A = x@W0 - x@W1, B = dinv*(x@W1) --------------------
// 512 threads = 16 warps x 4 nodes = 64 nodes/block. smem = 48KB exactly.
__global__ void __launch_bounds__(512) k_gemm1(const float* __restrict__ x,
                        const float* __restrict__ W0,
                        const float* __restrict__ W1, int N) {
    __shared__ float  Wsh[128 * 32];       // 16 KB
    __shared__ float4 xs[16][4][32];       // 32 KB
    int t = threadIdx.x;
    for (int i = t; i < 128 * 16; i += 512) {
        int k = i >> 4, j = i & 15;
        Wsh[k * 32 + j]      = W0[i];
        Wsh[k * 32 + 16 + j] = W1[i];
    }
    int warp = t >> 5, lane = t & 31;
    int base = (blockIdx.x * 16 + warp) * 4;

    #pragma unroll
    for (int n = 0; n < 4; n++) {
        int nd = base + n;
        float4 v = make_float4(0.f, 0.f, 0.f, 0.f);
        if (nd < N) v = ((const float4*)(x + (size_t)nd * 128))[lane];
        xs[warp][n][lane] = v;
    }
    __syncthreads();

    float a0 = 0.f, a1 = 0.f, a2 = 0.f, a3 = 0.f;
    #pragma unroll
    for (int k4 = 0; k4 < 32; k4++) {
        float w0 = Wsh[(k4 * 4 + 0) * 32 + lane];
        float w1 = Wsh[(k4 * 4 + 1) * 32 + lane];
        float w2 = Wsh[(k4 * 4 + 2) * 32 + lane];
        float w3 = Wsh[(k4 * 4 + 3) * 32 + lane];
        float4 b0 = xs[warp][0][k4];
        float4 b1 = xs[warp][1][k4];
        float4 b2 = xs[warp][2][k4];
        float4 b3 = xs[warp][3][k4];
        a0 = fmaf(b0.x, w0, fmaf(b0.y, w1, fmaf(b0.z, w2, fmaf(b0.w, w3, a0))));
        a1 = fmaf(b1.x, w0, fmaf(b1.y, w1, fmaf(b1.z, w2, fmaf(b1.w, w3, a1))));
        a2 = fmaf(b2.x, w0, fmaf(b2.y, w1, fmaf(b2.z, w2, fmaf(b2.w, w3, a2))));
        a3 = fmaf(b3.x, w0, fmaf(b3.y, w1, fmaf(b3.z, w2, fmaf(b3.w, w3, a3))));
    }

    float* A = (float*)g_A4;
    float* B = (float*)g_B4;
    float acc[4] = {a0, a1, a2, a3};
    #pragma unroll
    for (int n = 0; n < 4; n++) {
        int nd = base + n;
        float a = acc[n];
        float o = __shfl_xor_sync(0xffffffffu, a, 16);
        if (nd < N) {
            if (lane < 16) A[(size_t)nd * 16 + lane] = a - o;   // xp0 - xp1
            else {
                float dv = g_dinv[nd];
                B[(size_t)nd * 16 + (lane - 16)] = dv * a;      // dinv*xp1
            }
        }
    }
}

// ---------------- layer1: h = relu(A + dinv*agg(B) + b1) ---------------------
__global__ void k_layer1(const float* __restrict__ b1, int N) {
    int t = blockIdx.x * blockDim.x + threadIdx.x;
    int row = t >> 5;
    if (row >= N) return;
    int lane = t & 31, q = lane & 3, slot = lane >> 2;
    int s = g_rps[row];
    int e = g_rps[row + 1];
    float4 acc = make_float4(0.f, 0.f, 0.f, 0.f);
    for (int p = s + slot; p < e; p += 8) {
        int2 ce = g_csr[p];
        float nv = __int_as_float(ce.y);
        float4 v = g_B4[(size_t)ce.x * 4 + q];
        acc.x = fmaf(nv, v.x, acc.x);
        acc.y = fmaf(nv, v.y, acc.y);
        acc.z = fmaf(nv, v.z, acc.z);
        acc.w = fmaf(nv, v.w, acc.w);
    }
    #pragma unroll
    for (int d = 4; d < 32; d <<= 1) {
        acc.x += __shfl_xor_sync(0xffffffffu, acc.x, d);
        acc.y += __shfl_xor_sync(0xffffffffu, acc.y, d);
        acc.z += __shfl_xor_sync(0xffffffffu, acc.z, d);
        acc.w += __shfl_xor_sync(0xffffffffu, acc.w, d);
    }
    if (lane < 4) {
        float dv = g_dinv[row];
        float4 A  = g_A4[(size_t)row * 4 + lane];
        float4 bb = ((const float4*)b1)[lane];
        float4 h;
        h.x = fmaxf(A.x + dv * acc.x + bb.x, 0.f);
        h.y = fmaxf(A.y + dv * acc.y + bb.y, 0.f);
        h.z = fmaxf(A.z + dv * acc.z + bb.z, 0.f);
        h.w = fmaxf(A.w + dv * acc.w + bb.w, 0.f);
        g_h4[(size_t)row * 4 + lane]  = h;
        g_hs4[(size_t)row * 4 + lane] = make_float4(dv * h.x, dv * h.y, dv * h.z, dv * h.w);
    }
}

// ---------------- layer2: agg(hs) + dual GEMV + log_softmax ------------------
__global__ void k_layer2(const float* __restrict__ W20,
                         const float* __restrict__ W21,
                         const float* __restrict__ b2,
                         float* __restrict__ out, int N) {
    __shared__ float Wd[16 * 32];   // W20 - W21
    __shared__ float Wb[16 * 32];   // W21
    int t = threadIdx.x;
    for (int i = t; i < 512; i += blockDim.x) {
        float w1v = W21[i];
        Wd[i] = W20[i] - w1v;
        Wb[i] = w1v;
    }
    __syncthreads();
    int gt = blockIdx.x * blockDim.x + t;
    int row = gt >> 5;
    if (row >= N) return;
    int lane = t & 31, q = lane & 3, slot = lane >> 2;
    int s = g_rps[row];
    int e = g_rps[row + 1];
    float4 acc = make_float4(0.f, 0.f, 0.f, 0.f);
    for (int p = s + slot; p < e; p += 8) {
        int2 ce = g_csr[p];
        float nv = __int_as_float(ce.y);
        float4 v = g_hs4[(size_t)ce.x * 4 + q];
        acc.x = fmaf(nv, v.x, acc.x);
        acc.y = fmaf(nv, v.y, acc.y);
        acc.z = fmaf(nv, v.z, acc.z);
        acc.w = fmaf(nv, v.w, acc.w);
    }
    #pragma unroll
    for (int d = 4; d < 32; d <<= 1) {
        acc.x += __shfl_xor_sync(0xffffffffu, acc.x, d);
        acc.y += __shfl_xor_sync(0xffffffffu, acc.y, d);
        acc.z += __shfl_xor_sync(0xffffffffu, acc.z, d);
        acc.w += __shfl_xor_sync(0xffffffffu, acc.w, d);
    }
    float4 hv = make_float4(0.f, 0.f, 0.f, 0.f);
    if (lane < 4) hv = g_h4[(size_t)row * 4 + lane];
    float dv = g_dinv[row];

    float sh = 0.f, sa = 0.f;
    #pragma unroll
    for (int f = 0; f < 16; f++) {
        int src = f >> 2;
        float ch, ca;
        if ((f & 3) == 0)      { ch = hv.x; ca = acc.x; }
        else if ((f & 3) == 1) { ch = hv.y; ca = acc.y; }
        else if ((f & 3) == 2) { ch = hv.z; ca = acc.z; }
        else                   { ch = hv.w; ca = acc.w; }
        float hf = __shfl_sync(0xffffffffu, ch, src);
        float af = __shfl_sync(0xffffffffu, ca, src);
        sh = fmaf(hf, Wd[f * 32 + lane], sh);
        sa = fmaf(af, Wb[f * 32 + lane], sa);
    }
    float val = sh + dv * sa + __ldg(&b2[lane]);

    float m = val;
    #pragma unroll
    for (int d = 16; d; d >>= 1) m = fmaxf(m, __shfl_xor_sync(0xffffffffu, m, d));
    float ex = __expf(val - m);
    float sum = ex;
    #pragma unroll
    for (int d = 16; d; d >>= 1) sum += __shfl_xor_sync(0xffffffffu, sum, d);
    out[(size_t)row * 32 + lane] = val - m - __logf(sum);
}

// ---------------- launcher ----------------------------------------------------
extern "C" void kernel_launch(void* const* d_in, const int* in_sizes, int n_in,
                              void* d_out, int out_size) {
    const float* x   = (const float*)d_in[0];
    const void*  ei  = d_in[1];
    const float* ew  = (const float*)d_in[2];
    const float* W10 = (const float*)d_in[3];
    const float* W11 = (const float*)d_in[4];
    const float* b1  = (const float*)d_in[5];
    const float* W20 = (const float*)d_in[6];
    const float* W21 = (const float*)d_in[7];
    const float* b2  = (const float*)d_in[8];
    float* out = (float*)d_out;

    int N = in_sizes[0] / 128;
    int E = in_sizes[2];
    int NB = (N + 2047) / 2048;

    k_cnt<<<(E / 2 + 255) / 256, 256>>>(ei, E);
    k_scan_local<<<NB, 1024>>>(N, E, NB);
    k_scatter<<<(E + 255) / 256, 256>>>(ei, ew, E);
    k_dinv<<<(N * 32 + 255) / 256, 256>>>(N, E);
    k_gemm1<<<(N + 63) / 64, 512>>>(x, W10, W11, N);
    k_layer1<<<(N * 32 + 255) / 256, 256>>>(b1, N);
    k_layer2<<<(N * 32 + 255) / 256, 256>>>(W20, W21, b2, out, N);
}

// round 6
// speedup vs baseline: 1.4661x; 1.0377x over previous
#include <cuda_runtime.h>
#include <math.h>

#define MAXN 102400
#define MAXE 1605632
#define NBMAX 64

// ---------------- device scratch (zero-initialized at module load) -----------
__device__ int    g_cnt[MAXN];           // per-row counts (re-zeroed by scatter)
__device__ float  g_deg[MAXN];           // weighted degree (re-zeroed by finalize)
__device__ int    g_rank[MAXE];          // within-row rank of each edge
__device__ int    g_rowptr[MAXN + 1];    // block-local exclusive starts
__device__ int    g_bsums[NBMAX];
__device__ int    g_boffs[NBMAX];        // block offsets (add to rowptr)
__device__ int    g_done;                // decoupled-scan counter (self-reset)
__device__ int    g_rps[MAXN + 1];       // GLOBAL row starts (written by finalize)
__device__ int2   g_csr[MAXE];           // (col, ew bits)
__device__ float4 g_A4[MAXN * 4];        // xp0 - xp1
__device__ float4 g_B4[MAXN * 4];        // dinv * xp1 (layer-1 gather target)
__device__ float4 g_h4[MAXN * 4];        // h = relu(...)
__device__ float4 g_hs4[MAXN * 4];       // dinv * h   (layer-2 gather target)
__device__ float  g_dinv[MAXN];

// ---------------- per-block edge-index dtype detection -----------------------
__device__ __forceinline__ int detect_is64(const int* w) {
    int bad = 0;
    #pragma unroll
    for (int j = 1; j < 128; j += 2) bad |= w[j];
    return bad == 0;
}

// ---------------- pass 1: counts + within-row rank (2 edges/thread) ----------
__global__ void k_cnt(const void* __restrict__ ei, int E) {
    __shared__ int s_is64;
    if (threadIdx.x == 0) s_is64 = detect_is64((const int*)ei);
    __syncthreads();
    int e = (blockIdx.x * blockDim.x + threadIdx.x) * 2;
    if (e >= E) return;
    int r0, r1 = -1;
    if (s_is64) {
        longlong2 v = *(const longlong2*)((const long long*)ei + e);
        r0 = (int)v.x;
        if (e + 1 < E) r1 = (int)v.y;
    } else {
        int2 v = *(const int2*)((const int*)ei + e);
        r0 = v.x;
        if (e + 1 < E) r1 = v.y;
    }
    g_rank[e] = atomicAdd(&g_cnt[r0], 1);
    if (r1 >= 0) g_rank[e + 1] = atomicAdd(&g_cnt[r1], 1);
}

// ---------------- scan: per-block local scan + decoupled block-offset scan ---
__global__ void k_scan_local(int N, int E, int NB) {
    __shared__ int warpSums[32];
    __shared__ int s_flag;
    int t = threadIdx.x;
    int base = blockIdx.x * 2048;
    int i0 = base + 2 * t, i1 = i0 + 1;
    int v0 = (i0 < N) ? g_cnt[i0] : 0;
    int v1 = (i1 < N) ? g_cnt[i1] : 0;
    int s = v0 + v1;
    int lane = t & 31, wid = t >> 5;
    int incl = s;
    #pragma unroll
    for (int d = 1; d < 32; d <<= 1) {
        int n = __shfl_up_sync(0xffffffffu, incl, d);
        if (lane >= d) incl += n;
    }
    if (lane == 31) warpSums[wid] = incl;
    __syncthreads();
    if (wid == 0) {
        int ws = warpSums[lane];
        int wi = ws;
        #pragma unroll
        for (int d = 1; d < 32; d <<= 1) {
            int n = __shfl_up_sync(0xffffffffu, wi, d);
            if (lane >= d) wi += n;
        }
        warpSums[lane] = wi - ws;
    }
    __syncthreads();
    int excl = warpSums[wid] + incl - s;
    if (i0 < N) g_rowptr[i0] = excl;
    if (i1 < N) g_rowptr[i1] = excl + v0;
    if (t == 1023) g_bsums[blockIdx.x] = warpSums[wid] + incl;

    __syncthreads();
    if (t == 0) {
        __threadfence();
        s_flag = (atomicAdd(&g_done, 1) == NB - 1);
    }
    __syncthreads();
    if (s_flag && t < 32) {
        __threadfence();
        int b0 = (lane < NB) ? g_bsums[lane] : 0;
        int b1 = (lane + 32 < NB) ? g_bsums[lane + 32] : 0;
        int i0s = b0;
        #pragma unroll
        for (int d = 1; d < 32; d <<= 1) {
            int n = __shfl_up_sync(0xffffffffu, i0s, d);
            if (lane >= d) i0s += n;
        }
        int tot0 = __shfl_sync(0xffffffffu, i0s, 31);
        int i1s = b1;
        #pragma unroll
        for (int d = 1; d < 32; d <<= 1) {
            int n = __shfl_up_sync(0xffffffffu, i1s, d);
            if (lane >= d) i1s += n;
        }
        i1s += tot0;
        g_boffs[lane]      = i0s - b0;
        g_boffs[lane + 32] = i1s - b1;
        __syncwarp();
        if (lane == 0) g_done = 0;   // reset for next replay
    }
}

// ---------------- pass 2: scatter into CSR + weighted-degree REDG ------------
__global__ void k_scatter(const void* __restrict__ ei, const float* __restrict__ ew, int E) {
    __shared__ int s_is64;
    __shared__ int s_boffs[NBMAX];
    if (threadIdx.x == 0) s_is64 = detect_is64((const int*)ei);
    if (threadIdx.x < NBMAX) s_boffs[threadIdx.x] = g_boffs[threadIdx.x];
    __syncthreads();
    int e = blockIdx.x * blockDim.x + threadIdx.x;
    if (e < E) {
        int r, c;
        if (s_is64) {
            r = (int)((const long long*)ei)[e];
            c = (int)((const long long*)ei)[(long)E + e];
        } else {
            r = ((const int*)ei)[e];
            c = ((const int*)ei)[E + e];
        }
        float w = ew[e];
        int p = g_rowptr[r] + s_boffs[r >> 11] + g_rank[e];
        g_csr[p] = make_int2(c, __float_as_int(w));
        atomicAdd(&g_deg[r], w);            // REDG, no return
    }
    if (e < MAXN) g_cnt[e] = 0;   // reset counts for next graph replay
}

// ---------------- finalize: rps + dinv, thread per row (coalesced) -----------
__global__ void k_finalize(int N, int E) {
    __shared__ int s_boffs[NBMAX];
    if (threadIdx.x < NBMAX) s_boffs[threadIdx.x] = g_boffs[threadIdx.x];
    __syncthreads();
    int row = blockIdx.x * blockDim.x + threadIdx.x;
    if (row >= N) return;
    g_rps[row] = g_rowptr[row] + s_boffs[row >> 11];
    float d = g_deg[row];
    g_dinv[row] = (d > 0.f) ? rsqrtf(d) : 0.f;
    g_deg[row] = 0.f;                        // reset for next replay
    if (row == 0) g_rps[N] = E;
}

// ---------------- GEMM1: A = x@W0 - x@W1, B = dinv*(x@W1) --------------------
// 512 threads = 16 warps x 4 nodes = 64 nodes/block. smem = 48KB exactly.
__global__ void __launch_bounds__(512) k_gemm1(const float* __restrict__ x,
                        const float* __restrict__ W0,
                        const float* __restrict__ W1, int N) {
    __shared__ float  Wsh[128 * 32];       // 16 KB
    __shared__ float4 xs[16][4][32];       // 32 KB
    int t = threadIdx.x;
    for (int i = t; i < 128 * 16; i += 512) {
        int k = i >> 4, j = i & 15;
        Wsh[k * 32 + j]      = W0[i];
        Wsh[k * 32 + 16 + j] = W1[i];
    }
    int warp = t >> 5, lane = t & 31;
    int base = (blockIdx.x * 16 + warp) * 4;

    #pragma unroll
    for (int n = 0; n < 4; n++) {
        int nd = base + n;
        float4 v = make_float4(0.f, 0.f, 0.f, 0.f);
        if (nd < N) v = ((const float4*)(x + (size_t)nd * 128))[lane];
        xs[warp][n][lane] = v;
    }
    __syncthreads();

    float a0 = 0.f, a1 = 0.f, a2 = 0.f, a3 = 0.f;
    #pragma unroll
    for (int k4 = 0; k4 < 32; k4++) {
        float w0 = Wsh[(k4 * 4 + 0) * 32 + lane];
        float w1 = Wsh[(k4 * 4 + 1) * 32 + lane];
        float w2 = Wsh[(k4 * 4 + 2) * 32 + lane];
        float w3 = Wsh[(k4 * 4 + 3) * 32 + lane];
        float4 b0 = xs[warp][0][k4];
        float4 b1 = xs[warp][1][k4];
        float4 b2 = xs[warp][2][k4];
        float4 b3 = xs[warp][3][k4];
        a0 = fmaf(b0.x, w0, fmaf(b0.y, w1, fmaf(b0.z, w2, fmaf(b0.w, w3, a0))));
        a1 = fmaf(b1.x, w0, fmaf(b1.y, w1, fmaf(b1.z, w2, fmaf(b1.w, w3, a1))));
        a2 = fmaf(b2.x, w0, fmaf(b2.y, w1, fmaf(b2.z, w2, fmaf(b2.w, w3, a2))));
        a3 = fmaf(b3.x, w0, fmaf(b3.y, w1, fmaf(b3.z, w2, fmaf(b3.w, w3, a3))));
    }

    float* A = (float*)g_A4;
    float* B = (float*)g_B4;
    float acc[4] = {a0, a1, a2, a3};
    #pragma unroll
    for (int n = 0; n < 4; n++) {
        int nd = base + n;
        float a = acc[n];
        float o = __shfl_xor_sync(0xffffffffu, a, 16);
        if (nd < N) {
            if (lane < 16) A[(size_t)nd * 16 + lane] = a - o;   // xp0 - xp1
            else {
                float dv = g_dinv[nd];
                B[(size_t)nd * 16 + (lane - 16)] = dv * a;      // dinv*xp1
            }
        }
    }
}

// ---------------- layer1: h = relu(A + dinv*agg(B) + b1) ---------------------
__global__ void __launch_bounds__(1024) k_layer1(const float* __restrict__ b1, int N) {
    int t = blockIdx.x * blockDim.x + threadIdx.x;
    int row = t >> 5;
    if (row >= N) return;
    int lane = t & 31, q = lane & 3, slot = lane >> 2;
    int s = g_rps[row];
    int e = g_rps[row + 1];
    float4 acc = make_float4(0.f, 0.f, 0.f, 0.f);
    for (int p = s + slot; p < e; p += 8) {
        int2 ce = g_csr[p];
        float nv = __int_as_float(ce.y);
        float4 v = g_B4[(size_t)ce.x * 4 + q];
        acc.x = fmaf(nv, v.x, acc.x);
        acc.y = fmaf(nv, v.y, acc.y);
        acc.z = fmaf(nv, v.z, acc.z);
        acc.w = fmaf(nv, v.w, acc.w);
    }
    #pragma unroll
    for (int d = 4; d < 32; d <<= 1) {
        acc.x += __shfl_xor_sync(0xffffffffu, acc.x, d);
        acc.y += __shfl_xor_sync(0xffffffffu, acc.y, d);
        acc.z += __shfl_xor_sync(0xffffffffu, acc.z, d);
        acc.w += __shfl_xor_sync(0xffffffffu, acc.w, d);
    }
    if (lane < 4) {
        float dv = g_dinv[row];
        float4 A  = g_A4[(size_t)row * 4 + lane];
        float4 bb = ((const float4*)b1)[lane];
        float4 h;
        h.x = fmaxf(A.x + dv * acc.x + bb.x, 0.f);
        h.y = fmaxf(A.y + dv * acc.y + bb.y, 0.f);
        h.z = fmaxf(A.z + dv * acc.z + bb.z, 0.f);
        h.w = fmaxf(A.w + dv * acc.w + bb.w, 0.f);
        g_h4[(size_t)row * 4 + lane]  = h;
        g_hs4[(size_t)row * 4 + lane] = make_float4(dv * h.x, dv * h.y, dv * h.z, dv * h.w);
    }
}

// ---------------- layer2: agg(hs) + dual GEMV + log_softmax ------------------
__global__ void __launch_bounds__(1024) k_layer2(const float* __restrict__ W20,
                         const float* __restrict__ W21,
                         const float* __restrict__ b2,
                         float* __restrict__ out, int N) {
    __shared__ float Wd[16 * 32];   // W20 - W21
    __shared__ float Wb[16 * 32];   // W21
    int t = threadIdx.x;
    if (t < 512) {
        float w1v = W21[t];
        Wd[t] = W20[t] - w1v;
        Wb[t] = w1v;
    }
    __syncthreads();
    int gt = blockIdx.x * blockDim.x + t;
    int row = gt >> 5;
    if (row >= N) return;
    int lane = t & 31, q = lane & 3, slot = lane >> 2;
    int s = g_rps[row];
    int e = g_rps[row + 1];
    float4 acc = make_float4(0.f, 0.f, 0.f, 0.f);
    for (int p = s + slot; p < e; p += 8) {
        int2 ce = g_csr[p];
        float nv = __int_as_float(ce.y);
        float4 v = g_hs4[(size_t)ce.x * 4 + q];
        acc.x = fmaf(nv, v.x, acc.x);
        acc.y = fmaf(nv, v.y, acc.y);
        acc.z = fmaf(nv, v.z, acc.z);
        acc.w = fmaf(nv, v.w, acc.w);
    }
    #pragma unroll
    for (int d = 4; d < 32; d <<= 1) {
        acc.x += __shfl_xor_sync(0xffffffffu, acc.x, d);
        acc.y += __shfl_xor_sync(0xffffffffu, acc.y, d);
        acc.z += __shfl_xor_sync(0xffffffffu, acc.z, d);
        acc.w += __shfl_xor_sync(0xffffffffu, acc.w, d);
    }
    float4 hv = make_float4(0.f, 0.f, 0.f, 0.f);
    if (lane < 4) hv = g_h4[(size_t)row * 4 + lane];
    float dv = g_dinv[row];

    float sh = 0.f, sa = 0.f;
    #pragma unroll
    for (int f = 0; f < 16; f++) {
        int src = f >> 2;
        float ch, ca;
        if ((f & 3) == 0)      { ch = hv.x; ca = acc.x; }
        else if ((f & 3) == 1) { ch = hv.y; ca = acc.y; }
        else if ((f & 3) == 2) { ch = hv.z; ca = acc.z; }
        else                   { ch = hv.w; ca = acc.w; }
        float hf = __shfl_sync(0xffffffffu, ch, src);
        float af = __shfl_sync(0xffffffffu, ca, src);
        sh = fmaf(hf, Wd[f * 32 + lane], sh);
        sa = fmaf(af, Wb[f * 32 + lane], sa);
    }
    float val = sh + dv * sa + __ldg(&b2[lane]);

    float m = val;
    #pragma unroll
    for (int d = 16; d; d >>= 1) m = fmaxf(m, __shfl_xor_sync(0xffffffffu, m, d));
    float ex = __expf(val - m);
    float sum = ex;
    #pragma unroll
    for (int d = 16; d; d >>= 1) sum += __shfl_xor_sync(0xffffffffu, sum, d);
    out[(size_t)row * 32 + lane] = val - m - __logf(sum);
}

// ---------------- launcher ----------------------------------------------------
extern "C" void kernel_launch(void* const* d_in, const int* in_sizes, int n_in,
                              void* d_out, int out_size) {
    const float* x   = (const float*)d_in[0];
    const void*  ei  = d_in[1];
    const float* ew  = (const float*)d_in[2];
    const float* W10 = (const float*)d_in[3];
    const float* W11 = (const float*)d_in[4];
    const float* b1  = (const float*)d_in[5];
    const float* W20 = (const float*)d_in[6];
    const float* W21 = (const float*)d_in[7];
    const float* b2  = (const float*)d_in[8];
    float* out = (float*)d_out;

    int N = in_sizes[0] / 128;
    int E = in_sizes[2];
    int NB = (N + 2047) / 2048;

    k_cnt<<<(E / 2 + 255) / 256, 256>>>(ei, E);
    k_scan_local<<<NB, 1024>>>(N, E, NB);
    k_scatter<<<(E + 255) / 256, 256>>>(ei, ew, E);
    k_finalize<<<(N + 255) / 256, 256>>>(N, E);
    k_gemm1<<<(N + 63) / 64, 512>>>(x, W10, W11, N);
    k_layer1<<<(N * 32 + 1023) / 1024, 1024>>>(b1, N);
    k_layer2<<<(N * 32 + 1023) / 1024, 1024>>>(W20, W21, b2, out, N);
}

// round 7
// speedup vs baseline: 1.4792x; 1.0090x over previous
#include <cuda_runtime.h>
#include <math.h>

#define MAXN 102400
#define MAXE 1605632
#define NBMAX 64

// ---------------- device scratch (zero-initialized at module load) -----------
__device__ int    g_cnt[MAXN];           // per-row counts (re-zeroed by scatter)
__device__ float  g_deg[MAXN];           // weighted degree (re-zeroed by gemm1)
__device__ int    g_rank[MAXE];          // within-row rank of each edge
__device__ int    g_rowptr[MAXN + 1];    // block-local exclusive starts
__device__ int    g_bsums[NBMAX];
__device__ int    g_boffs[NBMAX];        // block offsets (add to rowptr)
__device__ int    g_done;                // decoupled-scan counter (self-reset)
__device__ int    g_rps[MAXN + 1];       // GLOBAL row starts (written by gemm1)
__device__ int2   g_csr[MAXE];           // (col, ew bits)
__device__ float4 g_A4[MAXN * 4];        // xp0 - xp1
__device__ float4 g_B4[MAXN * 4];        // dinv * xp1 (layer-1 gather target)
__device__ float4 g_h4[MAXN * 4];        // h = relu(...)
__device__ float4 g_hs4[MAXN * 4];       // dinv * h   (layer-2 gather target)
__device__ float  g_dinv[MAXN];

// ---------------- helpers -----------------------------------------------------
__device__ __forceinline__ int detect_is64(const int* w) {
    int bad = 0;
    #pragma unroll
    for (int j = 1; j < 128; j += 2) bad |= w[j];
    return bad == 0;
}

__device__ __forceinline__ unsigned long long pack_f2(float lo, float hi) {
    unsigned long long r;
    asm("mov.b64 %0, {%1, %2};" : "=l"(r) : "r"(__float_as_uint(lo)), "r"(__float_as_uint(hi)));
    return r;
}
__device__ __forceinline__ float f2_lo(unsigned long long v) {
    unsigned int lo, hi;
    asm("mov.b64 {%0, %1}, %2;" : "=r"(lo), "=r"(hi) : "l"(v));
    return __uint_as_float(lo);
}
__device__ __forceinline__ float f2_hi(unsigned long long v) {
    unsigned int lo, hi;
    asm("mov.b64 {%0, %1}, %2;" : "=r"(lo), "=r"(hi) : "l"(v));
    return __uint_as_float(hi);
}
#define FFMA2(acc, b, w) asm("fma.rn.f32x2 %0, %1, %2, %0;" : "+l"(acc) : "l"(b), "l"(w))

// ---------------- pass 1: counts + within-row rank (2 edges/thread) ----------
__global__ void k_cnt(const void* __restrict__ ei, int E) {
    __shared__ int s_is64;
    if (threadIdx.x == 0) s_is64 = detect_is64((const int*)ei);
    __syncthreads();
    int e = (blockIdx.x * blockDim.x + threadIdx.x) * 2;
    if (e >= E) return;
    int r0, r1 = -1;
    if (s_is64) {
        longlong2 v = *(const longlong2*)((const long long*)ei + e);
        r0 = (int)v.x;
        if (e + 1 < E) r1 = (int)v.y;
    } else {
        int2 v = *(const int2*)((const int*)ei + e);
        r0 = v.x;
        if (e + 1 < E) r1 = v.y;
    }
    g_rank[e] = atomicAdd(&g_cnt[r0], 1);
    if (r1 >= 0) g_rank[e + 1] = atomicAdd(&g_cnt[r1], 1);
}

// ---------------- scan: per-block local scan + decoupled block-offset scan ---
__global__ void k_scan_local(int N, int E, int NB) {
    __shared__ int warpSums[32];
    __shared__ int s_flag;
    int t = threadIdx.x;
    int base = blockIdx.x * 2048;
    int i0 = base + 2 * t, i1 = i0 + 1;
    int v0 = (i0 < N) ? g_cnt[i0] : 0;
    int v1 = (i1 < N) ? g_cnt[i1] : 0;
    int s = v0 + v1;
    int lane = t & 31, wid = t >> 5;
    int incl = s;
    #pragma unroll
    for (int d = 1; d < 32; d <<= 1) {
        int n = __shfl_up_sync(0xffffffffu, incl, d);
        if (lane >= d) incl += n;
    }
    if (lane == 31) warpSums[wid] = incl;
    __syncthreads();
    if (wid == 0) {
        int ws = warpSums[lane];
        int wi = ws;
        #pragma unroll
        for (int d = 1; d < 32; d <<= 1) {
            int n = __shfl_up_sync(0xffffffffu, wi, d);
            if (lane >= d) wi += n;
        }
        warpSums[lane] = wi - ws;
    }
    __syncthreads();
    int excl = warpSums[wid] + incl - s;
    if (i0 < N) g_rowptr[i0] = excl;
    if (i1 < N) g_rowptr[i1] = excl + v0;
    if (t == 1023) g_bsums[blockIdx.x] = warpSums[wid] + incl;

    __syncthreads();
    if (t == 0) {
        __threadfence();
        s_flag = (atomicAdd(&g_done, 1) == NB - 1);
    }
    __syncthreads();
    if (s_flag && t < 32) {
        __threadfence();
        int b0 = (lane < NB) ? g_bsums[lane] : 0;
        int b1 = (lane + 32 < NB) ? g_bsums[lane + 32] : 0;
        int i0s = b0;
        #pragma unroll
        for (int d = 1; d < 32; d <<= 1) {
            int n = __shfl_up_sync(0xffffffffu, i0s, d);
            if (lane >= d) i0s += n;
        }
        int tot0 = __shfl_sync(0xffffffffu, i0s, 31);
        int i1s = b1;
        #pragma unroll
        for (int d = 1; d < 32; d <<= 1) {
            int n = __shfl_up_sync(0xffffffffu, i1s, d);
            if (lane >= d) i1s += n;
        }
        i1s += tot0;
        g_boffs[lane]      = i0s - b0;
        g_boffs[lane + 32] = i1s - b1;
        __syncwarp();
        if (lane == 0) g_done = 0;   // reset for next replay
    }
}

// ---------------- pass 2: scatter into CSR + weighted-degree REDG ------------
__global__ void k_scatter(const void* __restrict__ ei, const float* __restrict__ ew, int E) {
    __shared__ int s_is64;
    __shared__ int s_boffs[NBMAX];
    if (threadIdx.x == 0) s_is64 = detect_is64((const int*)ei);
    if (threadIdx.x < NBMAX) s_boffs[threadIdx.x] = g_boffs[threadIdx.x];
    __syncthreads();
    int e = blockIdx.x * blockDim.x + threadIdx.x;
    if (e < E) {
        int r, c;
        if (s_is64) {
            r = (int)((const long long*)ei)[e];
            c = (int)((const long long*)ei)[(long)E + e];
        } else {
            r = ((const int*)ei)[e];
            c = ((const int*)ei)[E + e];
        }
        float w = ew[e];
        int p = g_rowptr[r] + s_boffs[r >> 11] + g_rank[e];
        g_csr[p] = make_int2(c, __float_as_int(w));
        atomicAdd(&g_deg[r], w);            // REDG, no return
    }
    if (e < MAXN) g_cnt[e] = 0;   // reset counts for next graph replay
}

// ---------------- GEMM1 (FFMA2) + fused finalize -----------------------------
// 512 threads = 16 warps x 4 nodes (2 f32x2 pairs). smem = 48KB + eps.
// Outputs: A = x@W0 - x@W1, B = dinv*(x@W1); also writes g_rps, g_dinv.
__global__ void __launch_bounds__(512) k_gemm1(const float* __restrict__ x,
                        const float* __restrict__ W0,
                        const float* __restrict__ W1, int N, int E) {
    __shared__ float Wsh[128 * 32];                      // 16 KB
    __shared__ unsigned long long xs2[16][2][128];       // 32 KB
    __shared__ float dvs[16][4];
    __shared__ int s_boffs[NBMAX];
    int t = threadIdx.x;
    if (t < NBMAX) s_boffs[t] = g_boffs[t];
    for (int i = t; i < 128 * 16; i += 512) {
        int k = i >> 4, j = i & 15;
        Wsh[k * 32 + j]      = W0[i];
        Wsh[k * 32 + 16 + j] = W1[i];
    }
    __syncthreads();   // s_boffs ready (Wsh consumed after 2nd sync)

    int warp = t >> 5, lane = t & 31;
    int base = (blockIdx.x * 16 + warp) * 4;

    // fused finalize: rps + dinv for this warp's 4 nodes
    if (lane < 4) {
        int nd = base + lane;
        float dv = 0.f;
        if (nd < N) {
            g_rps[nd] = g_rowptr[nd] + s_boffs[nd >> 11];
            float d = g_deg[nd];
            dv = (d > 0.f) ? rsqrtf(d) : 0.f;
            g_dinv[nd] = dv;
            g_deg[nd] = 0.f;                 // reset for next replay
        }
        dvs[warp][lane] = dv;
    }
    if (blockIdx.x == 0 && t == 0) g_rps[N] = E;

    // stage x as node-pair-interleaved f32x2 (conflict-free: k = i*32+lane)
    #pragma unroll
    for (int p = 0; p < 2; p++) {
        int n0 = base + 2 * p, n1 = n0 + 1;
        const float* x0 = x + (size_t)n0 * 128;
        const float* x1 = x + (size_t)n1 * 128;
        #pragma unroll
        for (int i = 0; i < 4; i++) {
            float fa = (n0 < N) ? x0[i * 32 + lane] : 0.f;
            float fb = (n1 < N) ? x1[i * 32 + lane] : 0.f;
            xs2[warp][p][i * 32 + lane] = pack_f2(fa, fb);
        }
    }
    __syncthreads();

    unsigned long long acc0 = 0ull, acc1 = 0ull;   // (n0,n1), (n2,n3)
    #pragma unroll 16
    for (int k = 0; k < 128; k++) {
        float wk = Wsh[k * 32 + lane];
        unsigned long long w2 = pack_f2(wk, wk);
        unsigned long long b0 = xs2[warp][0][k];
        unsigned long long b1 = xs2[warp][1][k];
        FFMA2(acc0, b0, w2);
        FFMA2(acc1, b1, w2);
    }

    float* A = (float*)g_A4;
    float* B = (float*)g_B4;
    float accs[4] = { f2_lo(acc0), f2_hi(acc0), f2_lo(acc1), f2_hi(acc1) };
    #pragma unroll
    for (int n = 0; n < 4; n++) {
        int nd = base + n;
        float a = accs[n];
        float o = __shfl_xor_sync(0xffffffffu, a, 16);
        if (nd < N) {
            if (lane < 16) A[(size_t)nd * 16 + lane] = a - o;   // xp0 - xp1
            else {
                float dv = dvs[warp][n];
                B[(size_t)nd * 16 + (lane - 16)] = dv * a;      // dinv*xp1
            }
        }
    }
}

// ---------------- layer1: h = relu(A + dinv*agg(B) + b1) ---------------------
__global__ void __launch_bounds__(1024) k_layer1(const float* __restrict__ b1, int N) {
    int t = blockIdx.x * blockDim.x + threadIdx.x;
    int row = t >> 5;
    if (row >= N) return;
    int lane = t & 31, q = lane & 3, slot = lane >> 2;
    int s = g_rps[row];
    int e = g_rps[row + 1];
    float4 acc = make_float4(0.f, 0.f, 0.f, 0.f);
    for (int p = s + slot; p < e; p += 8) {
        int2 ce = g_csr[p];
        float nv = __int_as_float(ce.y);
        float4 v = g_B4[(size_t)ce.x * 4 + q];
        acc.x = fmaf(nv, v.x, acc.x);
        acc.y = fmaf(nv, v.y, acc.y);
        acc.z = fmaf(nv, v.z, acc.z);
        acc.w = fmaf(nv, v.w, acc.w);
    }
    #pragma unroll
    for (int d = 4; d < 32; d <<= 1) {
        acc.x += __shfl_xor_sync(0xffffffffu, acc.x, d);
        acc.y += __shfl_xor_sync(0xffffffffu, acc.y, d);
        acc.z += __shfl_xor_sync(0xffffffffu, acc.z, d);
        acc.w += __shfl_xor_sync(0xffffffffu, acc.w, d);
    }
    if (lane < 4) {
        float dv = g_dinv[row];
        float4 A  = g_A4[(size_t)row * 4 + lane];
        float4 bb = ((const float4*)b1)[lane];
        float4 h;
        h.x = fmaxf(A.x + dv * acc.x + bb.x, 0.f);
        h.y = fmaxf(A.y + dv * acc.y + bb.y, 0.f);
        h.z = fmaxf(A.z + dv * acc.z + bb.z, 0.f);
        h.w = fmaxf(A.w + dv * acc.w + bb.w, 0.f);
        g_h4[(size_t)row * 4 + lane]  = h;
        g_hs4[(size_t)row * 4 + lane] = make_float4(dv * h.x, dv * h.y, dv * h.z, dv * h.w);
    }
}

// ---------------- layer2: agg(hs) + dual GEMV + log_softmax ------------------
__global__ void __launch_bounds__(1024) k_layer2(const float* __restrict__ W20,
                         const float* __restrict__ W21,
                         const float* __restrict__ b2,
                         float* __restrict__ out, int N) {
    __shared__ float Wd[16 * 32];   // W20 - W21
    __shared__ float Wb[16 * 32];   // W21
    int t = threadIdx.x;
    if (t < 512) {
        float w1v = W21[t];
        Wd[t] = W20[t] - w1v;
        Wb[t] = w1v;
    }
    __syncthreads();
    int gt = blockIdx.x * blockDim.x + t;
    int row = gt >> 5;
    if (row >= N) return;
    int lane = t & 31, q = lane & 3, slot = lane >> 2;
    int s = g_rps[row];
    int e = g_rps[row + 1];
    float4 acc = make_float4(0.f, 0.f, 0.f, 0.f);
    for (int p = s + slot; p < e; p += 8) {
        int2 ce = g_csr[p];
        float nv = __int_as_float(ce.y);
        float4 v = g_hs4[(size_t)ce.x * 4 + q];
        acc.x = fmaf(nv, v.x, acc.x);
        acc.y = fmaf(nv, v.y, acc.y);
        acc.z = fmaf(nv, v.z, acc.z);
        acc.w = fmaf(nv, v.w, acc.w);
    }
    #pragma unroll
    for (int d = 4; d < 32; d <<= 1) {
        acc.x += __shfl_xor_sync(0xffffffffu, acc.x, d);
        acc.y += __shfl_xor_sync(0xffffffffu, acc.y, d);
        acc.z += __shfl_xor_sync(0xffffffffu, acc.z, d);
        acc.w += __shfl_xor_sync(0xffffffffu, acc.w, d);
    }
    float4 hv = make_float4(0.f, 0.f, 0.f, 0.f);
    if (lane < 4) hv = g_h4[(size_t)row * 4 + lane];
    float dv = g_dinv[row];

    float sh = 0.f, sa = 0.f;
    #pragma unroll
    for (int f = 0; f < 16; f++) {
        int src = f >> 2;
        float ch, ca;
        if ((f & 3) == 0)      { ch = hv.x; ca = acc.x; }
        else if ((f & 3) == 1) { ch = hv.y; ca = acc.y; }
        else if ((f & 3) == 2) { ch = hv.z; ca = acc.z; }
        else                   { ch = hv.w; ca = acc.w; }
        float hf = __shfl_sync(0xffffffffu, ch, src);
        float af = __shfl_sync(0xffffffffu, ca, src);
        sh = fmaf(hf, Wd[f * 32 + lane], sh);
        sa = fmaf(af, Wb[f * 32 + lane], sa);
    }
    float val = sh + dv * sa + __ldg(&b2[lane]);

    float m = val;
    #pragma unroll
    for (int d = 16; d; d >>= 1) m = fmaxf(m, __shfl_xor_sync(0xffffffffu, m, d));
    float ex = __expf(val - m);
    float sum = ex;
    #pragma unroll
    for (int d = 16; d; d >>= 1) sum += __shfl_xor_sync(0xffffffffu, sum, d);
    out[(size_t)row * 32 + lane] = val - m - __logf(sum);
}

// ---------------- launcher ----------------------------------------------------
extern "C" void kernel_launch(void* const* d_in, const int* in_sizes, int n_in,
                              void* d_out, int out_size) {
    const float* x   = (const float*)d_in[0];
    const void*  ei  = d_in[1];
    const float* ew  = (const float*)d_in[2];
    const float* W10 = (const float*)d_in[3];
    const float* W11 = (const float*)d_in[4];
    const float* b1  = (const float*)d_in[5];
    const float* W20 = (const float*)d_in[6];
    const float* W21 = (const float*)d_in[7];
    const float* b2  = (const float*)d_in[8];
    float* out = (float*)d_out;

    int N = in_sizes[0] / 128;
    int E = in_sizes[2];
    int NB = (N + 2047) / 2048;

    k_cnt<<<(E / 2 + 255) / 256, 256>>>(ei, E);
    k_scan_local<<<NB, 1024>>>(N, E, NB);
    k_scatter<<<(E + 255) / 256, 256>>>(ei, ew, E);
    k_gemm1<<<(N + 63) / 64, 512>>>(x, W10, W11, N, E);
    k_layer1<<<(N * 32 + 1023) / 1024, 1024>>>(b1, N);
    k_layer2<<<(N * 32 + 1023) / 1024, 1024>>>(W20, W21, b2, out, N);
}